// round 17
// baseline (speedup 1.0000x reference)
#include <cuda_runtime.h>
#include <cstdint>

#define B_DIM 8
#define C_DIM 4
#define T_DIM 262144
#define T4 (T_DIM / 4)                    // ulonglong2 (16B) chunks per channel

#define NTHREADS 128
#define BLK_PER_BATCH 64
#define NBLOCKS (BLK_PER_BATCH * B_DIM)   // 512
#define ITERS 8                           // 64 * 128 * 8 = 65536 = T4

#define NVALS 24                          // 16 cross + 4 sx + 4 sy per batch

typedef unsigned long long u64;

// Scratch (zero-init at load; last block resets -> clean state each replay)
__device__ float g_partial[B_DIM][NVALS];
__device__ unsigned int g_ticket;

__device__ __forceinline__ u64 ffma2(u64 a, u64 b, u64 c) {
    u64 d;
    asm("fma.rn.f32x2 %0, %1, %2, %3;" : "=l"(d) : "l"(a), "l"(b), "l"(c));
    return d;
}

// 128-bit load, L2-cached / L1-bypass (.cg): streaming data has zero L1 reuse.
__device__ __forceinline__ ulonglong2 ldg128_cg(const ulonglong2* p) {
    ulonglong2 v;
    asm("ld.global.cg.v2.b64 {%0, %1}, [%2];" : "=l"(v.x), "=l"(v.y) : "l"(p));
    return v;
}

__global__ void __launch_bounds__(NTHREADS) pit_polar_cg_kernel(
    const float* __restrict__ x, const float* __restrict__ y,
    float* __restrict__ out) {
    const int tid = threadIdx.x;
    const int lane = tid & 31;
    const int b = blockIdx.y;

    const int base = blockIdx.x * (NTHREADS * ITERS) + tid;
    const ulonglong2* __restrict__ x2 =
        (const ulonglong2*)(x + (long long)b * C_DIM * T_DIM) + base;
    const ulonglong2* __restrict__ y2 =
        (const ulonglong2*)(y + (long long)b * C_DIM * T_DIM) + base;

    u64 cross[16], sx[4], sy[4];
#pragma unroll
    for (int k = 0; k < 16; k++) cross[k] = 0ULL;
#pragma unroll
    for (int k = 0; k < 4; k++) { sx[k] = 0ULL; sy[k] = 0ULL; }

#pragma unroll
    for (int it = 0; it < ITERS; it++) {
        const int col = it * NTHREADS;
        ulonglong2 xv[C_DIM], yv[C_DIM];
#pragma unroll
        for (int c = 0; c < C_DIM; c++) {
            xv[c] = ldg128_cg(&x2[c * T4 + col]);
            yv[c] = ldg128_cg(&y2[c * T4 + col]);
        }
#pragma unroll
        for (int c = 0; c < C_DIM; c++) {
            sx[c] = ffma2(xv[c].x, xv[c].x, sx[c]);
            sx[c] = ffma2(xv[c].y, xv[c].y, sx[c]);
            sy[c] = ffma2(yv[c].x, yv[c].x, sy[c]);
            sy[c] = ffma2(yv[c].y, yv[c].y, sy[c]);
        }
#pragma unroll
        for (int i = 0; i < C_DIM; i++) {
#pragma unroll
            for (int j = 0; j < C_DIM; j++) {
                u64 a = cross[i * 4 + j];
                a = ffma2(xv[j].x, yv[i].x, a);
                a = ffma2(xv[j].y, yv[i].y, a);
                cross[i * 4 + j] = a;
            }
        }
    }

    // Unpack f32x2 accumulators -> scalars
    float v[16], sq[8];
#pragma unroll
    for (int k = 0; k < 16; k++) {
        float lo = __uint_as_float((unsigned)(cross[k] & 0xFFFFFFFFULL));
        float hi = __uint_as_float((unsigned)(cross[k] >> 32));
        v[k] = lo + hi;
    }
#pragma unroll
    for (int k = 0; k < 4; k++) {
        sq[k] = __uint_as_float((unsigned)(sx[k] & 0xFFFFFFFFULL)) +
                __uint_as_float((unsigned)(sx[k] >> 32));
        sq[4 + k] = __uint_as_float((unsigned)(sy[k] & 0xFFFFFFFFULL)) +
                    __uint_as_float((unsigned)(sy[k] >> 32));
    }

    // Butterfly warp reduction on the 16 cross sums (16 shuffles);
    // lane l (l<16) ends owning cross index bitrev4(l).
#pragma unroll
    for (int j = 0; j < 8; j++) {
        float send = (lane & 1) ? v[j] : v[j + 8];
        float recv = __shfl_xor_sync(0xffffffff, send, 1);
        v[j] = ((lane & 1) ? v[j + 8] : v[j]) + recv;
    }
#pragma unroll
    for (int j = 0; j < 4; j++) {
        float send = (lane & 2) ? v[j] : v[j + 4];
        float recv = __shfl_xor_sync(0xffffffff, send, 2);
        v[j] = ((lane & 2) ? v[j + 4] : v[j]) + recv;
    }
#pragma unroll
    for (int j = 0; j < 2; j++) {
        float send = (lane & 4) ? v[j] : v[j + 2];
        float recv = __shfl_xor_sync(0xffffffff, send, 4);
        v[j] = ((lane & 4) ? v[j + 2] : v[j]) + recv;
    }
    {
        float send = (lane & 8) ? v[0] : v[1];
        float recv = __shfl_xor_sync(0xffffffff, send, 8);
        v[0] = ((lane & 8) ? v[1] : v[0]) + recv;
    }
    v[0] += __shfl_xor_sync(0xffffffff, v[0], 16);
    const int idx = ((lane & 1) << 3) | ((lane & 2) << 1) |
                    ((lane & 4) >> 1) | ((lane & 8) >> 3);

    // Butterfly reduction for the 8 square sums (9 shuffles).
    // After steps, lane l owns sq index ((l&1)<<2)|(l&2)|((l&4)>>2).
#pragma unroll
    for (int j = 0; j < 4; j++) {
        float send = (lane & 1) ? sq[j] : sq[j + 4];
        float recv = __shfl_xor_sync(0xffffffff, send, 1);
        sq[j] = ((lane & 1) ? sq[j + 4] : sq[j]) + recv;
    }
#pragma unroll
    for (int j = 0; j < 2; j++) {
        float send = (lane & 2) ? sq[j] : sq[j + 2];
        float recv = __shfl_xor_sync(0xffffffff, send, 2);
        sq[j] = ((lane & 2) ? sq[j + 2] : sq[j]) + recv;
    }
    {
        float send = (lane & 4) ? sq[0] : sq[1];
        float recv = __shfl_xor_sync(0xffffffff, send, 4);
        sq[0] = ((lane & 4) ? sq[1] : sq[0]) + recv;
    }
    sq[0] += __shfl_xor_sync(0xffffffff, sq[0], 8);
    sq[0] += __shfl_xor_sync(0xffffffff, sq[0], 16);
    const int idx_sq = ((lane & 1) << 2) | (lane & 2) | ((lane & 4) >> 2);

    __shared__ float s_acc[NVALS];
    __shared__ float s_d[B_DIM * NVALS];
    __shared__ bool s_is_last;

    if (tid < NVALS) s_acc[tid] = 0.0f;
    __syncthreads();
    if (lane < 16) atomicAdd(&s_acc[idx], v[0]);
    if (lane >= 16 && lane < 24) atomicAdd(&s_acc[16 + idx_sq], sq[0]);
    __syncthreads();
    if (tid < NVALS) atomicAdd(&g_partial[b][tid], s_acc[tid]);

    // ---- last-block-done finalize ----
    __threadfence();
    if (tid == 0) {
        unsigned int t = atomicAdd(&g_ticket, 1u);
        s_is_last = (t == NBLOCKS - 1);
    }
    __syncthreads();
    if (!s_is_last) return;

    for (int k = tid; k < B_DIM * NVALS; k += NTHREADS)
        s_d[k] = __ldcg(&((const float*)g_partial)[k]);
    __syncthreads();

    if (tid == 0) {
        const float inv_t = 1.0f / (float)T_DIM;
        float total = 0.0f;
        for (int bb = 0; bb < B_DIM; bb++) {
            const float* pp = &s_d[bb * NVALS];
            // dist_ij * T = Sx_j + Sy_i - 2*Cross_ij
            float d[16];
#pragma unroll
            for (int i = 0; i < 4; i++)
#pragma unroll
                for (int j = 0; j < 4; j++)
                    d[i * 4 + j] = pp[16 + j] + pp[20 + i] - 2.0f * pp[i * 4 + j];
            float best = 3.4e38f;
            for (int p0 = 0; p0 < 4; p0++)
                for (int p1 = 0; p1 < 4; p1++) {
                    if (p1 == p0) continue;
                    for (int p2 = 0; p2 < 4; p2++) {
                        if (p2 == p0 || p2 == p1) continue;
                        int p3 = 6 - p0 - p1 - p2;
                        float c = d[0 * 4 + p0] + d[1 * 4 + p1] +
                                  d[2 * 4 + p2] + d[3 * 4 + p3];
                        best = fminf(best, c);
                    }
                }
            total += best * inv_t;
        }
        out[0] = total;
        g_ticket = 0;
    }
    for (int k = tid; k < B_DIM * NVALS; k += NTHREADS)
        ((float*)g_partial)[k] = 0.0f;
}

extern "C" void kernel_launch(void* const* d_in, const int* in_sizes, int n_in,
                              void* d_out, int out_size) {
    const float* x = (const float*)d_in[0];
    const float* y = (const float*)d_in[1];
    float* out = (float*)d_out;

    dim3 grid(BLK_PER_BATCH, B_DIM);
    pit_polar_cg_kernel<<<grid, NTHREADS>>>(x, y, out);
}